// round 6
// baseline (speedup 1.0000x reference)
#include <cuda_runtime.h>
#include <stdint.h>

typedef unsigned long long U64;

// ---------------- device scratch (allocation-free rule) ----------------------
__device__ float g_pre[4UL * 256 * 512 * 64];   // [t][gate][h][b]  (134 MB)
__device__ U64   g_ht[2][16384];                // h state, pair layout [k/2][b], ping-pong
__device__ unsigned g_bar;

// ---------------- f32x2 helpers ---------------------------------------------
__device__ __forceinline__ U64 pack2(float lo, float hi) {
    U64 r;
    asm("mov.b64 %0, {%1, %2};" : "=l"(r) : "r"(__float_as_int(lo)), "r"(__float_as_int(hi)));
    return r;
}
__device__ __forceinline__ void unpack2(U64 v, float& lo, float& hi) {
    int a, b;
    asm("mov.b64 {%0, %1}, %2;" : "=r"(a), "=r"(b) : "l"(v));
    lo = __int_as_float(a); hi = __int_as_float(b);
}
__device__ __forceinline__ void fma2(U64& d, U64 a, U64 b) {
    asm("fma.rn.f32x2 %0, %1, %2, %0;" : "+l"(d) : "l"(a), "l"(b));
}
__device__ __forceinline__ float sig_(float x) { return 1.0f / (1.0f + __expf(-x)); }
__device__ __forceinline__ float tanh_(float x) { return 2.0f * sig_(2.0f * x) - 1.0f; }

// ---------------- prep: reset barrier + zero h0 ------------------------------
__global__ void prep_kernel() {
    int i = blockIdx.x * 256 + threadIdx.x;
    if (i == 0) g_bar = 0u;
    if (i < 16384) g_ht[0][i] = 0ull;
}

// ---------------- Phase 1: gathered GEMM -------------------------------------
// grid = (16 [4 n-tiles x 4 gates], 256 [t]); block = 256
// tile: 64(b) x 128(h) x 16(k); thread tile 8x4, f32x2 over b-pairs
__global__ void __launch_bounds__(256) gemm_kernel(
    const int* __restrict__ x, const float* __restrict__ emb,
    const float* __restrict__ Wf, const float* __restrict__ Wi,
    const float* __restrict__ Wg, const float* __restrict__ Wo)
{
    __shared__ int   sIdx[1024];       // [p][b]
    __shared__ float sA[16 * 68];      // [kk][b], pad 68 (16B-aligned rows)
    __shared__ float sB[16 * 128];     // [kk][h]

    const int tid  = threadIdx.x;
    const int gate = blockIdx.x >> 2;
    const int n0   = (blockIdx.x & 3) * 128;
    const int t    = blockIdx.y;
    const float* __restrict__ W = (gate == 0) ? Wf : (gate == 1) ? Wi : (gate == 2) ? Wg : Wo;

    for (int s = tid; s < 1024; s += 256) {
        int p = s >> 6, bb = s & 63;
        sIdx[s] = x[(bb * 16 + p) * 256 + t];
    }
    __syncthreads();

    const int r  = tid >> 2;            // A-load row (b) 0..63
    const int q  = (tid & 3) << 2;      // A-load kk base 0,4,8,12
    const int kr = tid >> 4;            // B-load k row 0..15
    const int c8 = (tid & 15) << 3;     // B-load col base
    const int ty = tid >> 5;            // compute row group 0..7 (8 b's)
    const int tx = tid & 31;            // compute col group (4 h's)

    U64 acc[16];
#pragma unroll
    for (int i = 0; i < 16; ++i) acc[i] = 0ull;

    float4 ra, rb0, rb1;
    {   // prefetch kt = 0
        int tok = sIdx[r];
        ra = (tok == 0) ? make_float4(0.f, 0.f, 0.f, 0.f)
                        : *(const float4*)&emb[(size_t)tok * 256 + q];
        rb0 = *(const float4*)&W[(size_t)kr * 512 + n0 + c8];
        rb1 = *(const float4*)&W[(size_t)kr * 512 + n0 + c8 + 4];
    }
    for (int kt = 0; kt < 256; ++kt) {
        sA[(q + 0) * 68 + r] = ra.x;
        sA[(q + 1) * 68 + r] = ra.y;
        sA[(q + 2) * 68 + r] = ra.z;
        sA[(q + 3) * 68 + r] = ra.w;
        *(float4*)&sB[kr * 128 + c8]     = rb0;
        *(float4*)&sB[kr * 128 + c8 + 4] = rb1;
        __syncthreads();
        if (kt + 1 < 256) {
            int kn = kt + 1;
            int p = kn >> 4, i0 = (kn & 15) << 4;
            int tok = sIdx[(p << 6) + r];
            ra = (tok == 0) ? make_float4(0.f, 0.f, 0.f, 0.f)
                            : *(const float4*)&emb[(size_t)tok * 256 + i0 + q];
            size_t krow = (size_t)(kn * 16 + kr) * 512;
            rb0 = *(const float4*)&W[krow + n0 + c8];
            rb1 = *(const float4*)&W[krow + n0 + c8 + 4];
        }
#pragma unroll
        for (int kk = 0; kk < 16; ++kk) {
            const float* Ak = &sA[kk * 68 + ty * 8];
            ulonglong2 A01 = *(const ulonglong2*)(Ak);      // b pairs (0,1),(2,3)
            ulonglong2 A23 = *(const ulonglong2*)(Ak + 4);  // b pairs (4,5),(6,7)
            float4 bv = *(const float4*)&sB[kk * 128 + tx * 4];
            U64 b0 = pack2(bv.x, bv.x), b1 = pack2(bv.y, bv.y);
            U64 b2 = pack2(bv.z, bv.z), b3 = pack2(bv.w, bv.w);
            fma2(acc[0],  A01.x, b0); fma2(acc[1],  A01.x, b1);
            fma2(acc[2],  A01.x, b2); fma2(acc[3],  A01.x, b3);
            fma2(acc[4],  A01.y, b0); fma2(acc[5],  A01.y, b1);
            fma2(acc[6],  A01.y, b2); fma2(acc[7],  A01.y, b3);
            fma2(acc[8],  A23.x, b0); fma2(acc[9],  A23.x, b1);
            fma2(acc[10], A23.x, b2); fma2(acc[11], A23.x, b3);
            fma2(acc[12], A23.y, b0); fma2(acc[13], A23.y, b1);
            fma2(acc[14], A23.y, b2); fma2(acc[15], A23.y, b3);
        }
        __syncthreads();
    }
    // epilogue: pre[t][gate][h][b]
    size_t base = (size_t)(t * 4 + gate) * 512;
#pragma unroll
    for (int c = 0; c < 4; ++c) {
        int h = n0 + tx * 4 + c;
        float v0, v1, v2, v3, v4, v5, v6, v7;
        unpack2(acc[0 * 4 + c], v0, v1);
        unpack2(acc[1 * 4 + c], v2, v3);
        unpack2(acc[2 * 4 + c], v4, v5);
        unpack2(acc[3 * 4 + c], v6, v7);
        float* dst = &g_pre[(base + h) * 64 + ty * 8];
        *(float4*)dst       = make_float4(v0, v1, v2, v3);
        *(float4*)(dst + 4) = make_float4(v4, v5, v6, v7);
    }
}

// ---------------- Phase 2: persistent LSTM recurrence ------------------------
// grid = 128 CTAs (1/SM, all resident), block = 256.
// CTA r owns h columns r*4..r*4+3 for all 4 gates; thread = (b = tid&63, j = tid>>6).
__global__ void __launch_bounds__(256, 1) lstm_kernel(
    const float* __restrict__ Wfh, const float* __restrict__ Wih,
    const float* __restrict__ Wgh, const float* __restrict__ Woh,
    const float* __restrict__ Bf,  const float* __restrict__ Bi,
    const float* __restrict__ Bg,  const float* __restrict__ Bo,
    float* __restrict__ out)
{
    extern __shared__ U64 sm[];
    U64* sh2 = sm;           // 16384 u64 = 128 KB  [k2][b]
    U64* sW  = sm + 16384;   // 4096  u64 = 32 KB   [k2][j][gate]

    const int tid = threadIdx.x;
    const int b   = tid & 63;
    const int j   = tid >> 6;
    const int h0  = blockIdx.x * 4;
    const int h   = h0 + j;

    for (int i = tid; i < 4096; i += 256) {
        int k2 = i >> 4, jj = (i >> 2) & 3, g = i & 3;
        const float* W = (g == 0) ? Wfh : (g == 1) ? Wih : (g == 2) ? Wgh : Woh;
        sW[i] = pack2(W[(2 * k2) * 512 + h0 + jj], W[(2 * k2 + 1) * 512 + h0 + jj]);
    }
    const float bf = Bf[h], bi = Bi[h], bg = Bg[h], bo = Bo[h];
    float cst = 0.0f;

    for (int t = 0; t < 256; ++t) {
        const uint4* src = (const uint4*)g_ht[t & 1];
        uint4* dsh = (uint4*)sh2;
#pragma unroll
        for (int i = 0; i < 32; ++i) dsh[tid + i * 256] = __ldcg(src + tid + i * 256);
        __syncthreads();

        U64 a0 = 0, a1 = 0, a2 = 0, a3 = 0;
        const U64* hp = sh2 + b;
        const ulonglong2* wpj = ((const ulonglong2*)sW) + j * 2;
#pragma unroll 8
        for (int k2 = 0; k2 < 256; ++k2) {
            U64 hv = hp[k2 * 64];
            ulonglong2 w01 = wpj[k2 * 8];
            ulonglong2 w23 = wpj[k2 * 8 + 1];
            fma2(a0, hv, w01.x); fma2(a1, hv, w01.y);
            fma2(a2, hv, w23.x); fma2(a3, hv, w23.y);
        }
        float lo, hi, d0, d1, d2, d3;
        unpack2(a0, lo, hi); d0 = lo + hi;
        unpack2(a1, lo, hi); d1 = lo + hi;
        unpack2(a2, lo, hi); d2 = lo + hi;
        unpack2(a3, lo, hi); d3 = lo + hi;

        size_t pb = ((size_t)t * 4) * 512;
        float pf = g_pre[(pb + 0 * 512 + h) * 64 + b] + bf + d0;
        float pi = g_pre[(pb + 1 * 512 + h) * 64 + b] + bi + d1;
        float pg = g_pre[(pb + 2 * 512 + h) * 64 + b] + bg + d2;
        float po = g_pre[(pb + 3 * 512 + h) * 64 + b] + bo + d3;

        float f = sig_(pf), ii = sig_(pi), gg = tanh_(pg), o = sig_(po);
        cst = f * cst + ii * gg;
        float hval = o * tanh_(cst);

        float* hd = (float*)g_ht[(t + 1) & 1];
        hd[(h >> 1) * 128 + (b << 1) + (h & 1)] = hval;

        if (t == 255) {
            out[320 + b * 512 + h]         = hval;
            out[320 + 32768 + b * 512 + h] = cst;
        } else {
            // grid barrier: write(t) -> read(t+1)
            __threadfence();
            __syncthreads();
            if (tid == 0) {
                atomicAdd(&g_bar, 1u);
                unsigned goal = (unsigned)(t + 1) * gridDim.x;
                while (*((volatile unsigned*)&g_bar) < goal) { __nanosleep(64); }
                __threadfence();
            }
            __syncthreads();
        }
    }
}

// ---------------- Phase 3: output head ---------------------------------------
__global__ void head_kernel(const float* __restrict__ Wl, const float* __restrict__ bl,
                            float* __restrict__ out)
{
    int tid = threadIdx.x;
    if (tid >= 320) return;
    int b = tid / 5, o = tid % 5;
    const float* hrow = out + 320 + b * 512;
    float s = bl[o];
#pragma unroll 8
    for (int k = 0; k < 512; ++k) s += hrow[k] * Wl[k * 5 + o];
    out[b * 5 + o] = s;
}

// ---------------- launch -----------------------------------------------------
extern "C" void kernel_launch(void* const* d_in, const int* in_sizes, int n_in,
                              void* d_out, int out_size)
{
    const int*   x   = (const int*)d_in[0];
    const float* emb = (const float*)d_in[1];
    const float* Wfx = (const float*)d_in[2];
    const float* Wfh = (const float*)d_in[3];
    const float* bf  = (const float*)d_in[4];
    const float* Wix = (const float*)d_in[5];
    const float* Wih = (const float*)d_in[6];
    const float* bi  = (const float*)d_in[7];
    const float* Wgx = (const float*)d_in[8];
    const float* Wgh = (const float*)d_in[9];
    const float* bg  = (const float*)d_in[10];
    const float* Wox = (const float*)d_in[11];
    const float* Woh = (const float*)d_in[12];
    const float* bo  = (const float*)d_in[13];
    const float* Wl  = (const float*)d_in[14];
    const float* bl  = (const float*)d_in[15];
    float* out = (float*)d_out;

    cudaFuncSetAttribute(lstm_kernel, cudaFuncAttributeMaxDynamicSharedMemorySize, 163840);

    prep_kernel<<<64, 256>>>();
    dim3 g1(16, 256);
    gemm_kernel<<<g1, 256>>>(x, emb, Wfx, Wix, Wgx, Wox);
    lstm_kernel<<<128, 256, 163840>>>(Wfh, Wih, Wgh, Woh, bf, bi, bg, bo, out);
    head_kernel<<<1, 320>>>(Wl, bl, out);
}

// round 9
// speedup vs baseline: 2.8867x; 2.8867x over previous
#include <cuda_runtime.h>
#include <cuda_bf16.h>
#include <stdint.h>

typedef unsigned long long U64;

// ======================= device scratch (no allocs rule) =====================
__device__ float          g_pre[4UL * 256 * 512 * 64];   // [t][gate][h][b] 128MiB
__device__ __nv_bfloat16  g_Ah[16384UL * 4096];          // gathered emb, hi split [m][k]
__device__ __nv_bfloat16  g_Al[16384UL * 4096];          // lo split
__device__ __nv_bfloat16  g_Bh[4UL * 512 * 4096];        // W_x [gate][h][k], hi
__device__ __nv_bfloat16  g_Bl[4UL * 512 * 4096];        // lo
__device__ U64            g_ht[2][16384];                // h state pairs, ping-pong
__device__ unsigned       g_bar;

// ======================= helpers ============================================
__device__ __forceinline__ U64 pack2(float lo, float hi) {
    U64 r;
    asm("mov.b64 %0, {%1, %2};" : "=l"(r) : "r"(__float_as_int(lo)), "r"(__float_as_int(hi)));
    return r;
}
__device__ __forceinline__ void unpack2(U64 v, float& lo, float& hi) {
    int a, b;
    asm("mov.b64 {%0, %1}, %2;" : "=r"(a), "=r"(b) : "l"(v));
    lo = __int_as_float(a); hi = __int_as_float(b);
}
__device__ __forceinline__ void fma2(U64& d, U64 a, U64 b) {
    asm("fma.rn.f32x2 %0, %1, %2, %0;" : "+l"(d) : "l"(a), "l"(b));
}
__device__ __forceinline__ float sig_(float x)  { return 1.0f / (1.0f + __expf(-x)); }
__device__ __forceinline__ float tanh_(float x) { return 2.0f * sig_(2.0f * x) - 1.0f; }

__device__ __forceinline__ uint32_t smem_u32(const void* p) {
    uint32_t a;
    asm("{ .reg .u64 t; cvta.to.shared.u64 t, %1; cvt.u32.u64 %0, t; }" : "=r"(a) : "l"(p));
    return a;
}
__device__ __forceinline__ void cpa16(uint32_t dst, const void* src) {
    asm volatile("cp.async.cg.shared.global [%0], [%1], 16;" :: "r"(dst), "l"(src));
}
#define CPA_COMMIT()  asm volatile("cp.async.commit_group;" ::: "memory")
#define CPA_WAIT1()   asm volatile("cp.async.wait_group 1;" ::: "memory")
#define CPA_WAIT0()   asm volatile("cp.async.wait_group 0;" ::: "memory")

__device__ __forceinline__ uint32_t swz(uint32_t o) { return o ^ ((o >> 3) & 0x70); }

__device__ __forceinline__ void ldsm4(uint32_t& r0, uint32_t& r1, uint32_t& r2, uint32_t& r3,
                                      uint32_t addr) {
    asm volatile("ldmatrix.sync.aligned.m8n8.x4.shared.b16 {%0,%1,%2,%3}, [%4];"
                 : "=r"(r0), "=r"(r1), "=r"(r2), "=r"(r3) : "r"(addr));
}
__device__ __forceinline__ void mma16816(float* c, const uint32_t* a, const uint32_t* b) {
    asm volatile("mma.sync.aligned.m16n8k16.row.col.f32.bf16.bf16.f32 "
                 "{%0,%1,%2,%3}, {%4,%5,%6,%7}, {%8,%9}, {%0,%1,%2,%3};"
                 : "+f"(c[0]), "+f"(c[1]), "+f"(c[2]), "+f"(c[3])
                 : "r"(a[0]), "r"(a[1]), "r"(a[2]), "r"(a[3]), "r"(b[0]), "r"(b[1]));
}

// ======================= prep kernels =======================================
__global__ void prep_kernel() {
    int i = blockIdx.x * 256 + threadIdx.x;
    if (i == 0) g_bar = 0u;
    if (i < 16384) g_ht[0][i] = 0ull;
}

// W_x [4096 k][512 h] f32 -> [gate][512 h][4096 k] bf16 hi/lo (smem transpose)
__global__ void __launch_bounds__(256) prep_w_kernel(
    const float* __restrict__ Wf, const float* __restrict__ Wi,
    const float* __restrict__ Wg, const float* __restrict__ Wo)
{
    __shared__ float s[32][33];
    int bid = blockIdx.x;
    int kb = bid & 127, hb = (bid >> 7) & 15, g = bid >> 11;
    const float* __restrict__ W = (g == 0) ? Wf : (g == 1) ? Wi : (g == 2) ? Wg : Wo;
    int tid = threadIdx.x, c = tid & 31, r4 = (tid >> 5) * 4;
    int k0 = kb * 32, h0 = hb * 32;
#pragma unroll
    for (int r = 0; r < 4; ++r)
        s[r4 + r][c] = W[(size_t)(k0 + r4 + r) * 512 + h0 + c];
    __syncthreads();
#pragma unroll
    for (int r = 0; r < 4; ++r) {
        int hh = r4 + r;
        float v = s[c][hh];
        __nv_bfloat16 hi = __float2bfloat16(v);
        float lo = v - __bfloat162float(hi);
        size_t o = ((size_t)g * 512 + h0 + hh) * 4096 + k0 + c;
        g_Bh[o] = hi;
        g_Bl[o] = __float2bfloat16(lo);
    }
}

// gather emb rows per (t,b) -> g_Ah/g_Al [m=16384][k=4096] bf16
__global__ void __launch_bounds__(256) prep_a_kernel(
    const int* __restrict__ x, const float* __restrict__ emb)
{
    __shared__ int sTok[16];
    int m = blockIdx.x, t = m >> 6, b = m & 63;
    int tid = threadIdx.x;
    if (tid < 16) sTok[tid] = x[(b * 16 + tid) * 256 + t];
    __syncthreads();
    size_t base = (size_t)m * 4096;
#pragma unroll 4
    for (int p = 0; p < 16; ++p) {
        int tok = sTok[p];
        float v = (tok == 0) ? 0.0f : emb[(size_t)tok * 256 + tid];
        __nv_bfloat16 hi = __float2bfloat16(v);
        float lo = v - __bfloat162float(hi);
        g_Ah[base + p * 256 + tid] = hi;
        g_Al[base + p * 256 + tid] = __float2bfloat16(lo);
    }
}

// ======================= Phase 1: mma.sync bf16-split GEMM ===================
// grid = (16 [gate*4 + ntile], 128 [mtile]); block = 256 (8 warps).
// CTA tile 128m x 128n, K-chunk 64, double-buffered cp.async.
// Warp tile 64m x 32n via m16n8k16; 3 split products into same f32 accums.
// smem per stage: Ah(16K) Al(16K) Bh(16K) Bl(16K) = 64K; x2 stages = 128K.
#define ST_OFF(st) ((st) * 65536u)
__global__ void __launch_bounds__(256, 1) gemm_kernel() {
    extern __shared__ char smem[];
    const uint32_t sb = smem_u32(smem);
    const int tid  = threadIdx.x;
    const int wid  = tid >> 5, lane = tid & 31;
    const int g    = blockIdx.x >> 2;
    const int n0   = (blockIdx.x & 3) * 128;
    const int m0   = blockIdx.y * 128;
    const int wm   = wid >> 2;            // 0..1  (64-row slab)
    const int wn   = wid & 3;             // 0..3  (32-col slab)

    const __nv_bfloat16* __restrict__ Ah = g_Ah + (size_t)m0 * 4096;
    const __nv_bfloat16* __restrict__ Al = g_Al + (size_t)m0 * 4096;
    const __nv_bfloat16* __restrict__ Bh = g_Bh + ((size_t)g * 512 + n0) * 4096;
    const __nv_bfloat16* __restrict__ Bl = g_Bl + ((size_t)g * 512 + n0) * 4096;

    // ---- async loader: 4096 x 16B per chunk (A/B, hi/lo) --------------------
    auto load_chunk = [&](int st, int c) {
        const int k0 = c * 64;
        const uint32_t s0 = sb + ST_OFF(st);
#pragma unroll
        for (int j = 0; j < 4; ++j) {
            int a = tid + j * 256;                 // 0..1023
            int row = a >> 3, u = a & 7;
            uint32_t d = swz((uint32_t)(row * 128 + u * 16));
            const size_t go = (size_t)row * 4096 + k0 + u * 8;
            cpa16(s0 + d,          Ah + go);
            cpa16(s0 + 16384 + d,  Al + go);
            cpa16(s0 + 32768 + d,  Bh + go);
            cpa16(s0 + 49152 + d,  Bl + go);
        }
        CPA_COMMIT();
    };

    float acc[4][4][4];
#pragma unroll
    for (int i = 0; i < 4; ++i)
#pragma unroll
        for (int j = 0; j < 4; ++j)
#pragma unroll
            for (int r = 0; r < 4; ++r) acc[i][j][r] = 0.0f;

    // ldmatrix lane address components (SW128 row-major tiles)
    const uint32_t xr    = (uint32_t)(lane & 7) << 4;         // swizzle XOR
    const uint32_t aRowB = (uint32_t)(wm * 64 + (lane & 15)) * 128;
    const uint32_t aUsel = (uint32_t)(lane >> 4);             // k 16B-half
    const uint32_t bRowB = (uint32_t)(wn * 32 + ((lane >> 4) << 3) + (lane & 7)) * 128;
    const uint32_t bUsel = (uint32_t)((lane >> 3) & 1);

    load_chunk(0, 0);

    for (int c = 0; c < 64; ++c) {
        if (c + 1 < 64) { load_chunk((c + 1) & 1, c + 1); CPA_WAIT1(); }
        else            { CPA_WAIT0(); }
        __syncthreads();                      // chunk c visible to all

        const uint32_t s0 = sb + ST_OFF(c & 1);
        const uint32_t aBh = s0 + aRowB;
        const uint32_t aBl = s0 + 16384 + aRowB;
        const uint32_t bBh = s0 + 32768 + bRowB;
        const uint32_t bBl = s0 + 49152 + bRowB;

#pragma unroll
        for (int ks = 0; ks < 4; ++ks) {
            const uint32_t uA = ((uint32_t)(ks * 2) + aUsel) * 16 ^ xr;
            const uint32_t uB = ((uint32_t)(ks * 2) + bUsel) * 16 ^ xr;
            uint32_t aH[4][4], aL[4][4], bH[4][2], bL[4][2];
#pragma unroll
            for (int i = 0; i < 4; ++i) {
                ldsm4(aH[i][0], aH[i][1], aH[i][2], aH[i][3], aBh + i * 2048 + uA);
                ldsm4(aL[i][0], aL[i][1], aL[i][2], aL[i][3], aBl + i * 2048 + uA);
            }
#pragma unroll
            for (int jb = 0; jb < 2; ++jb) {
                ldsm4(bH[jb*2][0], bH[jb*2][1], bH[jb*2+1][0], bH[jb*2+1][1],
                      bBh + jb * 2048 + uB);
                ldsm4(bL[jb*2][0], bL[jb*2][1], bL[jb*2+1][0], bL[jb*2+1][1],
                      bBl + jb * 2048 + uB);
            }
#pragma unroll
            for (int i = 0; i < 4; ++i)
#pragma unroll
                for (int j = 0; j < 4; ++j) mma16816(acc[i][j], aH[i], bH[j]);
#pragma unroll
            for (int i = 0; i < 4; ++i)
#pragma unroll
                for (int j = 0; j < 4; ++j) mma16816(acc[i][j], aH[i], bL[j]);
#pragma unroll
            for (int i = 0; i < 4; ++i)
#pragma unroll
                for (int j = 0; j < 4; ++j) mma16816(acc[i][j], aL[i], bH[j]);
        }
        __syncthreads();                      // protect stage before next reuse
    }

    // ---- epilogue: g_pre[t][gate][h][b]; warp m-slab = one t ----------------
    const int t  = blockIdx.y * 2 + wm;       // m0 = by*128, wm*64 -> t const
    const size_t tb = (size_t)(t * 4 + g) * 512;
#pragma unroll
    for (int i = 0; i < 4; ++i) {
        const int b0 = i * 16 + (lane >> 2);
#pragma unroll
        for (int j = 0; j < 4; ++j) {
            const int h0 = n0 + wn * 32 + j * 8 + 2 * (lane & 3);
            float* p = g_pre + (tb + h0) * 64 + b0;
            p[0]      = acc[i][j][0];   // (h0,   b0)
            p[64]     = acc[i][j][1];   // (h0+1, b0)
            p[8]      = acc[i][j][2];   // (h0,   b0+8)
            p[64 + 8] = acc[i][j][3];   // (h0+1, b0+8)
        }
    }
}

__global__ void dummy_kernel() {}

// ======================= Phase 2: persistent LSTM (validated R6) =============
__global__ void __launch_bounds__(256, 1) lstm_kernel(
    const float* __restrict__ Wfh, const float* __restrict__ Wih,
    const float* __restrict__ Wgh, const float* __restrict__ Woh,
    const float* __restrict__ Bf,  const float* __restrict__ Bi,
    const float* __restrict__ Bg,  const float* __restrict__ Bo,
    float* __restrict__ out)
{
    extern __shared__ U64 sm[];
    U64* sh2 = sm;           // 16384 u64 = 128 KB  [k2][b]
    U64* sW  = sm + 16384;   // 4096  u64 = 32 KB   [k2][j][gate]

    const int tid = threadIdx.x;
    const int b   = tid & 63;
    const int j   = tid >> 6;
    const int h0  = blockIdx.x * 4;
    const int h   = h0 + j;

    for (int i = tid; i < 4096; i += 256) {
        int k2 = i >> 4, jj = (i >> 2) & 3, g = i & 3;
        const float* W = (g == 0) ? Wfh : (g == 1) ? Wih : (g == 2) ? Wgh : Woh;
        sW[i] = pack2(W[(2 * k2) * 512 + h0 + jj], W[(2 * k2 + 1) * 512 + h0 + jj]);
    }
    const float bf = Bf[h], bi = Bi[h], bg = Bg[h], bo = Bo[h];
    float cst = 0.0f;

    for (int t = 0; t < 256; ++t) {
        const uint4* src = (const uint4*)g_ht[t & 1];
        uint4* dsh = (uint4*)sh2;
#pragma unroll
        for (int i = 0; i < 32; ++i) dsh[tid + i * 256] = __ldcg(src + tid + i * 256);
        __syncthreads();

        U64 a0 = 0, a1 = 0, a2 = 0, a3 = 0;
        const U64* hp = sh2 + b;
        const ulonglong2* wpj = ((const ulonglong2*)sW) + j * 2;
#pragma unroll 8
        for (int k2 = 0; k2 < 256; ++k2) {
            U64 hv = hp[k2 * 64];
            ulonglong2 w01 = wpj[k2 * 8];
            ulonglong2 w23 = wpj[k2 * 8 + 1];
            fma2(a0, hv, w01.x); fma2(a1, hv, w01.y);
            fma2(a2, hv, w23.x); fma2(a3, hv, w23.y);
        }
        float lo, hi, d0, d1, d2, d3;
        unpack2(a0, lo, hi); d0 = lo + hi;
        unpack2(a1, lo, hi); d1 = lo + hi;
        unpack2(a2, lo, hi); d2 = lo + hi;
        unpack2(a3, lo, hi); d3 = lo + hi;

        size_t pb = ((size_t)t * 4) * 512;
        float pf = g_pre[(pb + 0 * 512 + h) * 64 + b] + bf + d0;
        float pi = g_pre[(pb + 1 * 512 + h) * 64 + b] + bi + d1;
        float pg = g_pre[(pb + 2 * 512 + h) * 64 + b] + bg + d2;
        float po = g_pre[(pb + 3 * 512 + h) * 64 + b] + bo + d3;

        float f = sig_(pf), ii = sig_(pi), gg = tanh_(pg), o = sig_(po);
        cst = f * cst + ii * gg;
        float hval = o * tanh_(cst);

        float* hd = (float*)g_ht[(t + 1) & 1];
        hd[(h >> 1) * 128 + (b << 1) + (h & 1)] = hval;

        if (t == 255) {
            out[320 + b * 512 + h]         = hval;
            out[320 + 32768 + b * 512 + h] = cst;
        } else {
            __threadfence();
            __syncthreads();
            if (tid == 0) {
                atomicAdd(&g_bar, 1u);
                unsigned goal = (unsigned)(t + 1) * gridDim.x;
                while (*((volatile unsigned*)&g_bar) < goal) { __nanosleep(64); }
                __threadfence();
            }
            __syncthreads();
        }
    }
}

// ======================= Phase 3: output head (parallel) =====================
__global__ void head_kernel(const float* __restrict__ Wl, const float* __restrict__ bl,
                            float* __restrict__ out)
{
    int b = blockIdx.x;
    int tid = threadIdx.x;          // 160 threads: o = tid/32, lane = tid%32
    int o = tid >> 5, lane = tid & 31;
    const float* hrow = out + 320 + b * 512;
    float s = 0.0f;
#pragma unroll 4
    for (int k = lane; k < 512; k += 32) s += hrow[k] * Wl[k * 5 + o];
#pragma unroll
    for (int m = 16; m; m >>= 1) s += __shfl_xor_sync(0xffffffffu, s, m);
    if (lane == 0) out[b * 5 + o] = s + bl[o];
}

// ======================= launch =============================================
extern "C" void kernel_launch(void* const* d_in, const int* in_sizes, int n_in,
                              void* d_out, int out_size)
{
    const int*   x   = (const int*)d_in[0];
    const float* emb = (const float*)d_in[1];
    const float* Wfx = (const float*)d_in[2];
    const float* Wfh = (const float*)d_in[3];
    const float* bf  = (const float*)d_in[4];
    const float* Wix = (const float*)d_in[5];
    const float* Wih = (const float*)d_in[6];
    const float* bi  = (const float*)d_in[7];
    const float* Wgx = (const float*)d_in[8];
    const float* Wgh = (const float*)d_in[9];
    const float* bg  = (const float*)d_in[10];
    const float* Wox = (const float*)d_in[11];
    const float* Woh = (const float*)d_in[12];
    const float* bo  = (const float*)d_in[13];
    const float* Wl  = (const float*)d_in[14];
    const float* bl  = (const float*)d_in[15];
    float* out = (float*)d_out;

    cudaFuncSetAttribute(gemm_kernel, cudaFuncAttributeMaxDynamicSharedMemorySize, 131072);
    cudaFuncSetAttribute(lstm_kernel, cudaFuncAttributeMaxDynamicSharedMemorySize, 163840);

    prep_kernel<<<64, 256>>>();
    prep_w_kernel<<<4 * 16 * 128, 256>>>(Wfx, Wix, Wgx, Wox);
    prep_a_kernel<<<16384, 256>>>(x, emb);
    gemm_kernel<<<dim3(16, 128), 256, 131072>>>();
    dummy_kernel<<<1, 32>>>();   // shifts ncu -s 5 -c 1 onto lstm_kernel
    lstm_kernel<<<128, 256, 163840>>>(Wfh, Wih, Wgh, Woh, bf, bi, bg, bo, out);
    head_kernel<<<64, 160>>>(Wl, bl, out);
}

// round 10
// speedup vs baseline: 4.1147x; 1.4254x over previous
#include <cuda_runtime.h>
#include <cuda_bf16.h>
#include <stdint.h>

typedef unsigned long long U64;

// ======================= device scratch (no allocs rule) =====================
__device__ float          g_pre[4UL * 256 * 512 * 64];   // [t][gate][h][b] 128MiB
__device__ __nv_bfloat16  g_Ah[16384UL * 4096];          // gathered emb, hi split [m][k]
__device__ __nv_bfloat16  g_Al[16384UL * 4096];          // lo split
__device__ __nv_bfloat16  g_Bh[4UL * 512 * 4096];        // W_x [gate][h][k], hi
__device__ __nv_bfloat16  g_Bl[4UL * 512 * 4096];        // lo
__device__ __nv_bfloat16  g_hh[2][64 * 512];             // h state bf16 hi, ping-pong [b][h]
__device__ __nv_bfloat16  g_hl[2][64 * 512];             // h state bf16 lo
__device__ unsigned       g_bar;

// ======================= helpers ============================================
__device__ __forceinline__ float sig_(float x)  { return 1.0f / (1.0f + __expf(-x)); }
__device__ __forceinline__ float tanh_(float x) { return 2.0f * sig_(2.0f * x) - 1.0f; }

__device__ __forceinline__ uint32_t smem_u32(const void* p) {
    uint32_t a;
    asm("{ .reg .u64 t; cvta.to.shared.u64 t, %1; cvt.u32.u64 %0, t; }" : "=r"(a) : "l"(p));
    return a;
}
__device__ __forceinline__ void cpa16(uint32_t dst, const void* src) {
    asm volatile("cp.async.cg.shared.global [%0], [%1], 16;" :: "r"(dst), "l"(src));
}
#define CPA_COMMIT()  asm volatile("cp.async.commit_group;" ::: "memory")
#define CPA_WAIT1()   asm volatile("cp.async.wait_group 1;" ::: "memory")
#define CPA_WAIT0()   asm volatile("cp.async.wait_group 0;" ::: "memory")

__device__ __forceinline__ uint32_t swz(uint32_t o) { return o ^ ((o >> 3) & 0x70); }

__device__ __forceinline__ void ldsm4(uint32_t& r0, uint32_t& r1, uint32_t& r2, uint32_t& r3,
                                      uint32_t addr) {
    asm volatile("ldmatrix.sync.aligned.m8n8.x4.shared.b16 {%0,%1,%2,%3}, [%4];"
                 : "=r"(r0), "=r"(r1), "=r"(r2), "=r"(r3) : "r"(addr));
}
__device__ __forceinline__ void mma16816(float* c, const uint32_t* a, const uint32_t* b) {
    asm volatile("mma.sync.aligned.m16n8k16.row.col.f32.bf16.bf16.f32 "
                 "{%0,%1,%2,%3}, {%4,%5,%6,%7}, {%8,%9}, {%0,%1,%2,%3};"
                 : "+f"(c[0]), "+f"(c[1]), "+f"(c[2]), "+f"(c[3])
                 : "r"(a[0]), "r"(a[1]), "r"(a[2]), "r"(a[3]), "r"(b[0]), "r"(b[1]));
}

// ======================= prep kernels =======================================
__global__ void prep_kernel() {
    if (blockIdx.x == 0 && threadIdx.x == 0) g_bar = 0u;
}

// W_x [4096 k][512 h] f32 -> [gate][512 h][4096 k] bf16 hi/lo (smem transpose)
__global__ void __launch_bounds__(256) prep_w_kernel(
    const float* __restrict__ Wf, const float* __restrict__ Wi,
    const float* __restrict__ Wg, const float* __restrict__ Wo)
{
    __shared__ float s[32][33];
    int bid = blockIdx.x;
    int kb = bid & 127, hb = (bid >> 7) & 15, g = bid >> 11;
    const float* __restrict__ W = (g == 0) ? Wf : (g == 1) ? Wi : (g == 2) ? Wg : Wo;
    int tid = threadIdx.x, c = tid & 31, r4 = (tid >> 5) * 4;
    int k0 = kb * 32, h0 = hb * 32;
#pragma unroll
    for (int r = 0; r < 4; ++r)
        s[r4 + r][c] = W[(size_t)(k0 + r4 + r) * 512 + h0 + c];
    __syncthreads();
#pragma unroll
    for (int r = 0; r < 4; ++r) {
        int hh = r4 + r;
        float v = s[c][hh];
        __nv_bfloat16 hi = __float2bfloat16(v);
        float lo = v - __bfloat162float(hi);
        size_t o = ((size_t)g * 512 + h0 + hh) * 4096 + k0 + c;
        g_Bh[o] = hi;
        g_Bl[o] = __float2bfloat16(lo);
    }
}

// gather emb rows per (t,b) -> g_Ah/g_Al [m=16384][k=4096] bf16
__global__ void __launch_bounds__(256) prep_a_kernel(
    const int* __restrict__ x, const float* __restrict__ emb)
{
    __shared__ int sTok[16];
    int m = blockIdx.x, t = m >> 6, b = m & 63;
    int tid = threadIdx.x;
    if (tid < 16) sTok[tid] = x[(b * 16 + tid) * 256 + t];
    __syncthreads();
    size_t base = (size_t)m * 4096;
#pragma unroll 4
    for (int p = 0; p < 16; ++p) {
        int tok = sTok[p];
        float v = (tok == 0) ? 0.0f : emb[(size_t)tok * 256 + tid];
        __nv_bfloat16 hi = __float2bfloat16(v);
        float lo = v - __bfloat162float(hi);
        g_Ah[base + p * 256 + tid] = hi;
        g_Al[base + p * 256 + tid] = __float2bfloat16(lo);
    }
}

// ======================= Phase 1: mma.sync bf16-split GEMM (validated R9) ====
#define ST_OFF(st) ((st) * 65536u)
__global__ void __launch_bounds__(256, 1) gemm_kernel() {
    extern __shared__ char smem[];
    const uint32_t sb = smem_u32(smem);
    const int tid  = threadIdx.x;
    const int wid  = tid >> 5, lane = tid & 31;
    const int g    = blockIdx.x >> 2;
    const int n0   = (blockIdx.x & 3) * 128;
    const int m0   = blockIdx.y * 128;
    const int wm   = wid >> 2;
    const int wn   = wid & 3;

    const __nv_bfloat16* __restrict__ Ah = g_Ah + (size_t)m0 * 4096;
    const __nv_bfloat16* __restrict__ Al = g_Al + (size_t)m0 * 4096;
    const __nv_bfloat16* __restrict__ Bh = g_Bh + ((size_t)g * 512 + n0) * 4096;
    const __nv_bfloat16* __restrict__ Bl = g_Bl + ((size_t)g * 512 + n0) * 4096;

    auto load_chunk = [&](int st, int c) {
        const int k0 = c * 64;
        const uint32_t s0 = sb + ST_OFF(st);
#pragma unroll
        for (int j = 0; j < 4; ++j) {
            int a = tid + j * 256;
            int row = a >> 3, u = a & 7;
            uint32_t d = swz((uint32_t)(row * 128 + u * 16));
            const size_t go = (size_t)row * 4096 + k0 + u * 8;
            cpa16(s0 + d,          Ah + go);
            cpa16(s0 + 16384 + d,  Al + go);
            cpa16(s0 + 32768 + d,  Bh + go);
            cpa16(s0 + 49152 + d,  Bl + go);
        }
        CPA_COMMIT();
    };

    float acc[4][4][4];
#pragma unroll
    for (int i = 0; i < 4; ++i)
#pragma unroll
        for (int j = 0; j < 4; ++j)
#pragma unroll
            for (int r = 0; r < 4; ++r) acc[i][j][r] = 0.0f;

    const uint32_t xr    = (uint32_t)(lane & 7) << 4;
    const uint32_t aRowB = (uint32_t)(wm * 64 + (lane & 15)) * 128;
    const uint32_t aUsel = (uint32_t)(lane >> 4);
    const uint32_t bRowB = (uint32_t)(wn * 32 + ((lane >> 4) << 3) + (lane & 7)) * 128;
    const uint32_t bUsel = (uint32_t)((lane >> 3) & 1);

    load_chunk(0, 0);

    for (int c = 0; c < 64; ++c) {
        if (c + 1 < 64) { load_chunk((c + 1) & 1, c + 1); CPA_WAIT1(); }
        else            { CPA_WAIT0(); }
        __syncthreads();

        const uint32_t s0 = sb + ST_OFF(c & 1);
        const uint32_t aBh = s0 + aRowB;
        const uint32_t aBl = s0 + 16384 + aRowB;
        const uint32_t bBh = s0 + 32768 + bRowB;
        const uint32_t bBl = s0 + 49152 + bRowB;

#pragma unroll
        for (int ks = 0; ks < 4; ++ks) {
            const uint32_t uA = ((uint32_t)(ks * 2) + aUsel) * 16 ^ xr;
            const uint32_t uB = ((uint32_t)(ks * 2) + bUsel) * 16 ^ xr;
            uint32_t aH[4][4], aL[4][4], bH[4][2], bL[4][2];
#pragma unroll
            for (int i = 0; i < 4; ++i) {
                ldsm4(aH[i][0], aH[i][1], aH[i][2], aH[i][3], aBh + i * 2048 + uA);
                ldsm4(aL[i][0], aL[i][1], aL[i][2], aL[i][3], aBl + i * 2048 + uA);
            }
#pragma unroll
            for (int jb = 0; jb < 2; ++jb) {
                ldsm4(bH[jb*2][0], bH[jb*2][1], bH[jb*2+1][0], bH[jb*2+1][1],
                      bBh + jb * 2048 + uB);
                ldsm4(bL[jb*2][0], bL[jb*2][1], bL[jb*2+1][0], bL[jb*2+1][1],
                      bBl + jb * 2048 + uB);
            }
#pragma unroll
            for (int i = 0; i < 4; ++i)
#pragma unroll
                for (int j = 0; j < 4; ++j) mma16816(acc[i][j], aH[i], bH[j]);
#pragma unroll
            for (int i = 0; i < 4; ++i)
#pragma unroll
                for (int j = 0; j < 4; ++j) mma16816(acc[i][j], aH[i], bL[j]);
#pragma unroll
            for (int i = 0; i < 4; ++i)
#pragma unroll
                for (int j = 0; j < 4; ++j) mma16816(acc[i][j], aL[i], bH[j]);
        }
        __syncthreads();
    }

    const int t  = blockIdx.y * 2 + wm;
    const size_t tb = (size_t)(t * 4 + g) * 512;
#pragma unroll
    for (int i = 0; i < 4; ++i) {
        const int b0 = i * 16 + (lane >> 2);
#pragma unroll
        for (int j = 0; j < 4; ++j) {
            const int h0 = n0 + wn * 32 + j * 8 + 2 * (lane & 3);
            float* p = g_pre + (tb + h0) * 64 + b0;
            p[0]      = acc[i][j][0];
            p[64]     = acc[i][j][1];
            p[8]      = acc[i][j][2];
            p[64 + 8] = acc[i][j][3];
        }
    }
}

__global__ void dummy_kernel() {}

// ======================= Phase 2: tensor-core persistent LSTM ================
// grid = 128 CTAs (1/SM), block = 128 (4 warps).
// CTA owns 16 N-cols: col c = j*4 + gate, h = blockIdx.x*4 + j.
// Per step: h (bf16 hi/lo) broadcast to smem, D = h @ Wh via m16n8k16 x3 products.
// Warp w owns b-rows 16w..16w+15; lane ends with 2 (b,h) cells after shfl swap.
// smem: A_hi 64KB | A_lo 64KB | W_hi 16KB | W_lo 16KB = 160KB.
__global__ void __launch_bounds__(128, 1) lstm_kernel(
    const float* __restrict__ Wfh, const float* __restrict__ Wih,
    const float* __restrict__ Wgh, const float* __restrict__ Woh,
    const float* __restrict__ Bf,  const float* __restrict__ Bi,
    const float* __restrict__ Bg,  const float* __restrict__ Bo,
    float* __restrict__ out)
{
    extern __shared__ char smem[];
    const uint32_t sb   = smem_u32(smem);
    const uint32_t sbAh = sb;
    const uint32_t sbAl = sb + 65536u;
    const uint32_t sbWh = sb + 131072u;
    const uint32_t sbWl = sb + 147456u;

    const int tid  = threadIdx.x;
    const int w    = tid >> 5, lane = tid & 31;
    const int hb   = blockIdx.x * 4;

    // ---- load W_h tile [16 c][512 k] bf16 hi/lo, swizzled 1KB rows ----------
    for (int i = 0; i < 64; ++i) {
        int idx = i * 128 + tid;               // 0..8191
        int c = idx >> 9, k = idx & 511;
        int gg = c & 3, j = c >> 2;
        const float* W = (gg == 0) ? Wfh : (gg == 1) ? Wih : (gg == 2) ? Wgh : Woh;
        float v = W[(size_t)k * 512 + hb + j];
        __nv_bfloat16 hi = __float2bfloat16(v);
        float lo = v - __bfloat162float(hi);
        uint32_t off = (uint32_t)c * 1024 + ((((uint32_t)k >> 3) ^ (uint32_t)(c & 7)) << 4)
                     + ((uint32_t)(k & 7) << 1);
        *(__nv_bfloat16*)(smem + (off))            = hi;   // sbWh region base handled below
        *(__nv_bfloat16*)(smem + (off + 16384u))   = __float2bfloat16(lo);
    }
    // NOTE: W written at smem offsets [0,32KB) temporarily — must move? No:
    // instead write directly to the W region:
    __syncthreads();
    // relocate W from [0,32K) to [131072,163840) (one-time, avoids addr math above)
    for (int i = tid; i < 8192; i += 128) {
        *(uint32_t*)(smem + 131072u + i * 4) = *(uint32_t*)(smem + i * 4);
    }
    __syncthreads();

    // per-lane cell mapping
    const int r    = lane >> 2;                 // 0..7
    const int odd  = lane & 1;
    const int b    = 16 * w + r + (odd ? 8 : 0);
    const int j0   = (lane >> 1) & 1;           // ntile0 -> h hb+j0 ; ntile1 -> hb+j0+2
    const int h_0  = hb + j0;
    const int h_1  = hb + j0 + 2;

    // ldmatrix address components
    const uint32_t aRow  = (uint32_t)(16 * w + (lane & 15));
    const uint32_t aBaseH = sbAh + aRow * 1024u;
    const uint32_t aBaseL = sbAl + aRow * 1024u;
    const uint32_t aXor  = aRow & 7u;
    const uint32_t aSel  = (uint32_t)(lane >> 4);
    const uint32_t bRow  = (uint32_t)(((lane >> 4) << 3) + (lane & 7));
    const uint32_t bBaseH = sbWh + bRow * 1024u;
    const uint32_t bBaseL = sbWl + bRow * 1024u;
    const uint32_t bXor  = bRow & 7u;
    const uint32_t bSel  = (uint32_t)((lane >> 3) & 1);

    float cst0 = 0.0f, cst1 = 0.0f;

    for (int t = 0; t < 256; ++t) {
        // ---- grid barrier (t>0): h(t) stores visible before broadcast -------
        if (t > 0) {
            __threadfence();
            __syncthreads();
            if (tid == 0) {
                atomicAdd(&g_bar, 1u);
                unsigned goal = (unsigned)t * gridDim.x;
                while (*((volatile unsigned*)&g_bar) < goal) { __nanosleep(32); }
                __threadfence();
            }
            __syncthreads();
        }

        // ---- broadcast h(t) bf16 hi/lo into smem (2 cp.async groups) --------
        if (t > 0) {
            const __nv_bfloat16* hh = g_hh[t & 1];
            const __nv_bfloat16* hl = g_hl[t & 1];
#pragma unroll
            for (int grp = 0; grp < 2; ++grp) {
#pragma unroll
                for (int i = 0; i < 16; ++i) {
                    int q = i * 128 + tid;            // 0..2047
                    int bb = q >> 5, uu = q & 31;
                    uint32_t u = (uint32_t)(grp * 32 + uu);
                    uint32_t d = (uint32_t)bb * 1024u + ((u ^ (uint32_t)(bb & 7)) << 4);
                    const size_t go = (size_t)bb * 512 + u * 8;
                    cpa16(sbAh + d, hh + go);
                    cpa16(sbAl + d, hl + go);
                }
                CPA_COMMIT();
            }
        }

        // ---- pre-activation loads (independent of h; issue early) -----------
        float pf0 = g_pre[((size_t)(t * 4 + 0) * 512 + h_0) * 64 + b];
        float pi0 = g_pre[((size_t)(t * 4 + 1) * 512 + h_0) * 64 + b];
        float pg0 = g_pre[((size_t)(t * 4 + 2) * 512 + h_0) * 64 + b];
        float po0 = g_pre[((size_t)(t * 4 + 3) * 512 + h_0) * 64 + b];
        float pf1 = g_pre[((size_t)(t * 4 + 0) * 512 + h_1) * 64 + b];
        float pi1 = g_pre[((size_t)(t * 4 + 1) * 512 + h_1) * 64 + b];
        float pg1 = g_pre[((size_t)(t * 4 + 2) * 512 + h_1) * 64 + b];
        float po1 = g_pre[((size_t)(t * 4 + 3) * 512 + h_1) * 64 + b];

        float c0[4] = {0.f, 0.f, 0.f, 0.f};
        float c1[4] = {0.f, 0.f, 0.f, 0.f};

        if (t > 0) {
#pragma unroll
            for (int half = 0; half < 2; ++half) {
                if (half == 0) { CPA_WAIT1(); } else { CPA_WAIT0(); }
                __syncthreads();
#pragma unroll
                for (int kk = 0; kk < 16; ++kk) {
                    const int kk16 = half * 16 + kk;
                    const uint32_t uA = (((uint32_t)(2 * kk16) + aSel) ^ aXor) << 4;
                    const uint32_t uB = (((uint32_t)(2 * kk16) + bSel) ^ bXor) << 4;
                    uint32_t aH[4], aL[4], bH[4], bL[4];
                    ldsm4(aH[0], aH[1], aH[2], aH[3], aBaseH + uA);
                    ldsm4(aL[0], aL[1], aL[2], aL[3], aBaseL + uA);
                    ldsm4(bH[0], bH[1], bH[2], bH[3], bBaseH + uB);
                    ldsm4(bL[0], bL[1], bL[2], bL[3], bBaseL + uB);
                    mma16816(c0, aH, bH);     mma16816(c1, aH, bH + 2);
                    mma16816(c0, aH, bL);     mma16816(c1, aH, bL + 2);
                    mma16816(c0, aL, bH);     mma16816(c1, aL, bH + 2);
                }
            }
        }

        // ---- fragment exchange: lane pairs swap so each lane has f,i,g,o ----
        float d0f, d0i, d0g, d0o, d1f, d1i, d1g, d1o;
        {
            float x0 = __shfl_xor_sync(0xffffffffu, c0[0], 1);
            float x1 = __shfl_xor_sync(0xffffffffu, c0[1], 1);
            float x2 = __shfl_xor_sync(0xffffffffu, c0[2], 1);
            float x3 = __shfl_xor_sync(0xffffffffu, c0[3], 1);
            if (!odd) { d0f = c0[0]; d0i = c0[1]; d0g = x0;   d0o = x1;   }
            else      { d0f = x2;    d0i = x3;    d0g = c0[2]; d0o = c0[3]; }
            float y0 = __shfl_xor_sync(0xffffffffu, c1[0], 1);
            float y1 = __shfl_xor_sync(0xffffffffu, c1[1], 1);
            float y2 = __shfl_xor_sync(0xffffffffu, c1[2], 1);
            float y3 = __shfl_xor_sync(0xffffffffu, c1[3], 1);
            if (!odd) { d1f = c1[0]; d1i = c1[1]; d1g = y0;   d1o = y1;   }
            else      { d1f = y2;    d1i = y3;    d1g = c1[2]; d1o = c1[3]; }
        }

        // ---- gate math + state update ---------------------------------------
        float f0 = sig_(pf0 + d0f + Bf[h_0]);
        float i0 = sig_(pi0 + d0i + Bi[h_0]);
        float gg0 = tanh_(pg0 + d0g + Bg[h_0]);
        float o0 = sig_(po0 + d0o + Bo[h_0]);
        cst0 = f0 * cst0 + i0 * gg0;
        float hv0 = o0 * tanh_(cst0);

        float f1 = sig_(pf1 + d1f + Bf[h_1]);
        float i1 = sig_(pi1 + d1i + Bi[h_1]);
        float gg1 = tanh_(pg1 + d1g + Bg[h_1]);
        float o1 = sig_(po1 + d1o + Bo[h_1]);
        cst1 = f1 * cst1 + i1 * gg1;
        float hv1 = o1 * tanh_(cst1);

        if (t == 255) {
            out[320 + b * 512 + h_0]         = hv0;
            out[320 + 32768 + b * 512 + h_0] = cst0;
            out[320 + b * 512 + h_1]         = hv1;
            out[320 + 32768 + b * 512 + h_1] = cst1;
        } else {
            __nv_bfloat16 h0h = __float2bfloat16(hv0);
            __nv_bfloat16 h0l = __float2bfloat16(hv0 - __bfloat162float(h0h));
            __nv_bfloat16 h1h = __float2bfloat16(hv1);
            __nv_bfloat16 h1l = __float2bfloat16(hv1 - __bfloat162float(h1h));
            const int nb = (t + 1) & 1;
            g_hh[nb][b * 512 + h_0] = h0h;  g_hl[nb][b * 512 + h_0] = h0l;
            g_hh[nb][b * 512 + h_1] = h1h;  g_hl[nb][b * 512 + h_1] = h1l;
        }
    }
}

// ======================= Phase 3: output head ================================
__global__ void head_kernel(const float* __restrict__ Wl, const float* __restrict__ bl,
                            float* __restrict__ out)
{
    int b = blockIdx.x;
    int tid = threadIdx.x;
    int o = tid >> 5, lane = tid & 31;
    const float* hrow = out + 320 + b * 512;
    float s = 0.0f;
#pragma unroll 4
    for (int k = lane; k < 512; k += 32) s += hrow[k] * Wl[k * 5 + o];
#pragma unroll
    for (int m = 16; m; m >>= 1) s += __shfl_xor_sync(0xffffffffu, s, m);
    if (lane == 0) out[b * 5 + o] = s + bl[o];
}

// ======================= launch =============================================
extern "C" void kernel_launch(void* const* d_in, const int* in_sizes, int n_in,
                              void* d_out, int out_size)
{
    const int*   x   = (const int*)d_in[0];
    const float* emb = (const float*)d_in[1];
    const float* Wfx = (const float*)d_in[2];
    const float* Wfh = (const float*)d_in[3];
    const float* bf  = (const float*)d_in[4];
    const float* Wix = (const float*)d_in[5];
    const float* Wih = (const float*)d_in[6];
    const float* bi  = (const float*)d_in[7];
    const float* Wgx = (const float*)d_in[8];
    const float* Wgh = (const float*)d_in[9];
    const float* bg  = (const float*)d_in[10];
    const float* Wox = (const float*)d_in[11];
    const float* Woh = (const float*)d_in[12];
    const float* bo  = (const float*)d_in[13];
    const float* Wl  = (const float*)d_in[14];
    const float* bl  = (const float*)d_in[15];
    float* out = (float*)d_out;

    cudaFuncSetAttribute(gemm_kernel, cudaFuncAttributeMaxDynamicSharedMemorySize, 131072);
    cudaFuncSetAttribute(lstm_kernel, cudaFuncAttributeMaxDynamicSharedMemorySize, 163840);

    prep_kernel<<<1, 32>>>();
    prep_w_kernel<<<4 * 16 * 128, 256>>>(Wfx, Wix, Wgx, Wox);
    prep_a_kernel<<<16384, 256>>>(x, emb);
    gemm_kernel<<<dim3(16, 128), 256, 131072>>>();
    dummy_kernel<<<1, 32>>>();   // shifts ncu -s 5 -c 1 onto lstm_kernel
    lstm_kernel<<<128, 128, 163840>>>(Wfh, Wih, Wgh, Woh, bf, bi, bg, bo, out);
    head_kernel<<<64, 160>>>(Wl, bl, out);
}

// round 11
// speedup vs baseline: 4.5171x; 1.0978x over previous
#include <cuda_runtime.h>
#include <cuda_bf16.h>
#include <stdint.h>

typedef unsigned long long U64;

// ======================= device scratch (no allocs rule) =====================
__device__ float          g_pre[4UL * 256 * 512 * 64];   // [t][gate][h][b] 128MiB
__device__ __nv_bfloat16  g_Ah[16384UL * 4096];          // gathered emb, hi split [m][k]
__device__ __nv_bfloat16  g_Al[16384UL * 4096];          // lo split
__device__ __nv_bfloat16  g_Bh[4UL * 512 * 4096];        // W_x [gate][h][k], hi
__device__ __nv_bfloat16  g_Bl[4UL * 512 * 4096];        // lo
__device__ __nv_bfloat16  g_hh[2][64 * 512];             // h state bf16 hi, ping-pong [b][h]
__device__ __nv_bfloat16  g_hl[2][64 * 512];             // h state bf16 lo
__device__ unsigned       g_bar;

// ======================= helpers ============================================
__device__ __forceinline__ float sig_(float x)  { return 1.0f / (1.0f + __expf(-x)); }
__device__ __forceinline__ float tanh_(float x) { return 2.0f * sig_(2.0f * x) - 1.0f; }

__device__ __forceinline__ uint32_t smem_u32(const void* p) {
    uint32_t a;
    asm("{ .reg .u64 t; cvta.to.shared.u64 t, %1; cvt.u32.u64 %0, t; }" : "=r"(a) : "l"(p));
    return a;
}
__device__ __forceinline__ void cpa16(uint32_t dst, const void* src) {
    asm volatile("cp.async.cg.shared.global [%0], [%1], 16;" :: "r"(dst), "l"(src));
}
#define CPA_COMMIT()  asm volatile("cp.async.commit_group;" ::: "memory")
#define CPA_WAIT0()   asm volatile("cp.async.wait_group 0;" ::: "memory")
#define CPA_WAIT1()   asm volatile("cp.async.wait_group 1;" ::: "memory")
#define CPA_WAIT2()   asm volatile("cp.async.wait_group 2;" ::: "memory")
#define CPA_WAIT3()   asm volatile("cp.async.wait_group 3;" ::: "memory")

__device__ __forceinline__ uint32_t swz(uint32_t o) { return o ^ ((o >> 3) & 0x70); }

__device__ __forceinline__ void ldsm4(uint32_t& r0, uint32_t& r1, uint32_t& r2, uint32_t& r3,
                                      uint32_t addr) {
    asm volatile("ldmatrix.sync.aligned.m8n8.x4.shared.b16 {%0,%1,%2,%3}, [%4];"
                 : "=r"(r0), "=r"(r1), "=r"(r2), "=r"(r3) : "r"(addr));
}
__device__ __forceinline__ void mma16816(float* c, const uint32_t* a, const uint32_t* b) {
    asm volatile("mma.sync.aligned.m16n8k16.row.col.f32.bf16.bf16.f32 "
                 "{%0,%1,%2,%3}, {%4,%5,%6,%7}, {%8,%9}, {%0,%1,%2,%3};"
                 : "+f"(c[0]), "+f"(c[1]), "+f"(c[2]), "+f"(c[3])
                 : "r"(a[0]), "r"(a[1]), "r"(a[2]), "r"(a[3]), "r"(b[0]), "r"(b[1]));
}
__device__ __forceinline__ void bar_arrive_release(unsigned* p) {
    asm volatile("red.release.gpu.add.u32 [%0], %1;" :: "l"(p), "r"(1u) : "memory");
}
__device__ __forceinline__ unsigned ld_acquire(unsigned* p) {
    unsigned v;
    asm volatile("ld.acquire.gpu.u32 %0, [%1];" : "=r"(v) : "l"(p) : "memory");
    return v;
}

// ======================= prep kernels =======================================
__global__ void prep_kernel() {
    if (blockIdx.x == 0 && threadIdx.x == 0) g_bar = 0u;
}

// W_x [4096 k][512 h] f32 -> [gate][512 h][4096 k] bf16 hi/lo (smem transpose)
__global__ void __launch_bounds__(256) prep_w_kernel(
    const float* __restrict__ Wf, const float* __restrict__ Wi,
    const float* __restrict__ Wg, const float* __restrict__ Wo)
{
    __shared__ float s[32][33];
    int bid = blockIdx.x;
    int kb = bid & 127, hb = (bid >> 7) & 15, g = bid >> 11;
    const float* __restrict__ W = (g == 0) ? Wf : (g == 1) ? Wi : (g == 2) ? Wg : Wo;
    int tid = threadIdx.x, c = tid & 31, r4 = (tid >> 5) * 4;
    int k0 = kb * 32, h0 = hb * 32;
#pragma unroll
    for (int r = 0; r < 4; ++r)
        s[r4 + r][c] = W[(size_t)(k0 + r4 + r) * 512 + h0 + c];
    __syncthreads();
#pragma unroll
    for (int r = 0; r < 4; ++r) {
        int hh = r4 + r;
        float v = s[c][hh];
        __nv_bfloat16 hi = __float2bfloat16(v);
        float lo = v - __bfloat162float(hi);
        size_t o = ((size_t)g * 512 + h0 + hh) * 4096 + k0 + c;
        g_Bh[o] = hi;
        g_Bl[o] = __float2bfloat16(lo);
    }
}

// gather emb rows per (t,b) -> g_Ah/g_Al [m=16384][k=4096] bf16 (u32 writes)
__global__ void __launch_bounds__(128) prep_a_kernel(
    const int* __restrict__ x, const float* __restrict__ emb)
{
    __shared__ int sTok[16];
    int m = blockIdx.x, t = m >> 6, b = m & 63;
    int tid = threadIdx.x;                       // 0..127 -> i pair
    if (tid < 16) sTok[tid] = x[(b * 16 + tid) * 256 + t];
    __syncthreads();
    uint32_t* Ah32 = (uint32_t*)g_Ah;
    uint32_t* Al32 = (uint32_t*)g_Al;
    size_t base2 = (size_t)m * 2048;             // u32 index
#pragma unroll 4
    for (int p = 0; p < 16; ++p) {
        int tok = sTok[p];
        float2 v = (tok == 0) ? make_float2(0.f, 0.f)
                              : ((const float2*)emb)[(size_t)tok * 128 + tid];
        __nv_bfloat16 h0 = __float2bfloat16(v.x);
        __nv_bfloat16 h1 = __float2bfloat16(v.y);
        __nv_bfloat16 l0 = __float2bfloat16(v.x - __bfloat162float(h0));
        __nv_bfloat16 l1 = __float2bfloat16(v.y - __bfloat162float(h1));
        uint32_t hv = (uint32_t)__bfloat16_as_ushort(h0) |
                      ((uint32_t)__bfloat16_as_ushort(h1) << 16);
        uint32_t lv = (uint32_t)__bfloat16_as_ushort(l0) |
                      ((uint32_t)__bfloat16_as_ushort(l1) << 16);
        Ah32[base2 + p * 128 + tid] = hv;
        Al32[base2 + p * 128 + tid] = lv;
    }
}

// ======================= Phase 1: mma.sync bf16-split GEMM (3-stage) =========
// grid = (16 [gate*4 + ntile], 128 [mtile]); block = 256 (8 warps).
// CTA tile 128m x 128n, K-chunk 64, 3-stage cp.async, ONE sync per chunk.
#define ST_OFF(st) ((uint32_t)(st) * 65536u)
__global__ void __launch_bounds__(256, 1) gemm_kernel() {
    extern __shared__ char smem[];
    const uint32_t sb = smem_u32(smem);
    const int tid  = threadIdx.x;
    const int wid  = tid >> 5, lane = tid & 31;
    const int g    = blockIdx.x >> 2;
    const int n0   = (blockIdx.x & 3) * 128;
    const int m0   = blockIdx.y * 128;
    const int wm   = wid >> 2;
    const int wn   = wid & 3;

    const __nv_bfloat16* __restrict__ Ah = g_Ah + (size_t)m0 * 4096;
    const __nv_bfloat16* __restrict__ Al = g_Al + (size_t)m0 * 4096;
    const __nv_bfloat16* __restrict__ Bh = g_Bh + ((size_t)g * 512 + n0) * 4096;
    const __nv_bfloat16* __restrict__ Bl = g_Bl + ((size_t)g * 512 + n0) * 4096;

    auto load_chunk = [&](int st, int c) {
        const int k0 = c * 64;
        const uint32_t s0 = sb + ST_OFF(st);
#pragma unroll
        for (int j = 0; j < 4; ++j) {
            int a = tid + j * 256;
            int row = a >> 3, u = a & 7;
            uint32_t d = swz((uint32_t)(row * 128 + u * 16));
            const size_t go = (size_t)row * 4096 + k0 + u * 8;
            cpa16(s0 + d,          Ah + go);
            cpa16(s0 + 16384 + d,  Al + go);
            cpa16(s0 + 32768 + d,  Bh + go);
            cpa16(s0 + 49152 + d,  Bl + go);
        }
        CPA_COMMIT();
    };

    float acc[4][4][4];
#pragma unroll
    for (int i = 0; i < 4; ++i)
#pragma unroll
        for (int j = 0; j < 4; ++j)
#pragma unroll
            for (int r = 0; r < 4; ++r) acc[i][j][r] = 0.0f;

    const uint32_t xr    = (uint32_t)(lane & 7) << 4;
    const uint32_t aRowB = (uint32_t)(wm * 64 + (lane & 15)) * 128;
    const uint32_t aUsel = (uint32_t)(lane >> 4);
    const uint32_t bRowB = (uint32_t)(wn * 32 + ((lane >> 4) << 3) + (lane & 7)) * 128;
    const uint32_t bUsel = (uint32_t)((lane >> 3) & 1);

    load_chunk(0, 0);
    load_chunk(1, 1);

    int st = 0;                                   // stage of chunk c
    for (int c = 0; c < 64; ++c) {
        if (c == 63) { CPA_WAIT0(); } else { CPA_WAIT1(); }
        __syncthreads();                          // chunk c visible; all past mma(c-1)

        const uint32_t s0 = sb + ST_OFF(st);
        const uint32_t aBh = s0 + aRowB;
        const uint32_t aBl = s0 + 16384 + aRowB;
        const uint32_t bBh = s0 + 32768 + bRowB;
        const uint32_t bBl = s0 + 49152 + bRowB;

#pragma unroll
        for (int ks = 0; ks < 4; ++ks) {
            const uint32_t uA = ((uint32_t)(ks * 2) + aUsel) * 16 ^ xr;
            const uint32_t uB = ((uint32_t)(ks * 2) + bUsel) * 16 ^ xr;
            uint32_t aH[4][4], aL[4][4], bH[4][2], bL[4][2];
#pragma unroll
            for (int i = 0; i < 4; ++i) {
                ldsm4(aH[i][0], aH[i][1], aH[i][2], aH[i][3], aBh + i * 2048 + uA);
                ldsm4(aL[i][0], aL[i][1], aL[i][2], aL[i][3], aBl + i * 2048 + uA);
            }
#pragma unroll
            for (int jb = 0; jb < 2; ++jb) {
                ldsm4(bH[jb*2][0], bH[jb*2][1], bH[jb*2+1][0], bH[jb*2+1][1],
                      bBh + jb * 2048 + uB);
                ldsm4(bL[jb*2][0], bL[jb*2][1], bL[jb*2+1][0], bL[jb*2+1][1],
                      bBl + jb * 2048 + uB);
            }
#pragma unroll
            for (int i = 0; i < 4; ++i)
#pragma unroll
                for (int j = 0; j < 4; ++j) mma16816(acc[i][j], aH[i], bH[j]);
#pragma unroll
            for (int i = 0; i < 4; ++i)
#pragma unroll
                for (int j = 0; j < 4; ++j) mma16816(acc[i][j], aH[i], bL[j]);
#pragma unroll
            for (int i = 0; i < 4; ++i)
#pragma unroll
                for (int j = 0; j < 4; ++j) mma16816(acc[i][j], aL[i], bH[j]);
        }

        // prefetch chunk c+2 into stage (c+2)%3 = (c-1)%3: every warp is past
        // the iter-c barrier, hence past mma(c-1) reads of that stage. Safe.
        if (c + 2 < 64) {
            int stn = st + 2; if (stn >= 3) stn -= 3;
            load_chunk(stn, c + 2);
        }
        if (++st == 3) st = 0;
    }

    const int t  = blockIdx.y * 2 + wm;
    const size_t tb = (size_t)(t * 4 + g) * 512;
#pragma unroll
    for (int i = 0; i < 4; ++i) {
        const int b0 = i * 16 + (lane >> 2);
#pragma unroll
        for (int j = 0; j < 4; ++j) {
            const int h0 = n0 + wn * 32 + j * 8 + 2 * (lane & 3);
            float* p = g_pre + (tb + h0) * 64 + b0;
            p[0]      = acc[i][j][0];
            p[64]     = acc[i][j][1];
            p[8]      = acc[i][j][2];
            p[64 + 8] = acc[i][j][3];
        }
    }
}

__global__ void dummy_kernel() {}

// ======================= Phase 2: tensor-core persistent LSTM ================
// grid = 128 CTAs (1/SM), block = 128 (4 warps). bf16 3-product (validated).
// New: release/acquire barrier (no membar.gpu), broadcast in 4 pipelined groups.
__global__ void __launch_bounds__(128, 1) lstm_kernel(
    const float* __restrict__ Wfh, const float* __restrict__ Wih,
    const float* __restrict__ Wgh, const float* __restrict__ Woh,
    const float* __restrict__ Bf,  const float* __restrict__ Bi,
    const float* __restrict__ Bg,  const float* __restrict__ Bo,
    float* __restrict__ out)
{
    extern __shared__ char smem[];
    const uint32_t sb   = smem_u32(smem);
    const uint32_t sbAh = sb;
    const uint32_t sbAl = sb + 65536u;
    const uint32_t sbWh = sb + 131072u;
    const uint32_t sbWl = sb + 147456u;

    const int tid  = threadIdx.x;
    const int w    = tid >> 5, lane = tid & 31;
    const int hb   = blockIdx.x * 4;

    // ---- load W_h tile [16 c][512 k] bf16 hi/lo (staged at 0, relocated) ----
    for (int i = 0; i < 64; ++i) {
        int idx = i * 128 + tid;
        int c = idx >> 9, k = idx & 511;
        int gg = c & 3, j = c >> 2;
        const float* W = (gg == 0) ? Wfh : (gg == 1) ? Wih : (gg == 2) ? Wgh : Woh;
        float v = W[(size_t)k * 512 + hb + j];
        __nv_bfloat16 hi = __float2bfloat16(v);
        float lo = v - __bfloat162float(hi);
        uint32_t off = (uint32_t)c * 1024 + ((((uint32_t)k >> 3) ^ (uint32_t)(c & 7)) << 4)
                     + ((uint32_t)(k & 7) << 1);
        *(__nv_bfloat16*)(smem + (off))          = hi;
        *(__nv_bfloat16*)(smem + (off + 16384u)) = __float2bfloat16(lo);
    }
    __syncthreads();
    for (int i = tid; i < 8192; i += 128) {
        *(uint32_t*)(smem + 131072u + i * 4) = *(uint32_t*)(smem + i * 4);
    }
    __syncthreads();

    const int r    = lane >> 2;
    const int odd  = lane & 1;
    const int b    = 16 * w + r + (odd ? 8 : 0);
    const int j0   = (lane >> 1) & 1;
    const int h_0  = hb + j0;
    const int h_1  = hb + j0 + 2;

    const uint32_t aRow   = (uint32_t)(16 * w + (lane & 15));
    const uint32_t aBaseH = sbAh + aRow * 1024u;
    const uint32_t aBaseL = sbAl + aRow * 1024u;
    const uint32_t aXor   = aRow & 7u;
    const uint32_t aSel   = (uint32_t)(lane >> 4);
    const uint32_t bRow   = (uint32_t)(((lane >> 4) << 3) + (lane & 7));
    const uint32_t bBaseH = sbWh + bRow * 1024u;
    const uint32_t bBaseL = sbWl + bRow * 1024u;
    const uint32_t bXor   = bRow & 7u;
    const uint32_t bSel   = (uint32_t)((lane >> 3) & 1);

    const float bf0 = Bf[h_0], bi0 = Bi[h_0], bg0 = Bg[h_0], bo0 = Bo[h_0];
    const float bf1 = Bf[h_1], bi1 = Bi[h_1], bg1 = Bg[h_1], bo1 = Bo[h_1];

    float cst0 = 0.0f, cst1 = 0.0f;

    for (int t = 0; t < 256; ++t) {
        if (t > 0) {
            // acquire barrier: all CTAs' step-(t-1) h stores visible
            if (tid == 0) {
                unsigned goal = (unsigned)t * 128u;
                while (ld_acquire(&g_bar) < goal) { }
            }
            __syncthreads();

            // broadcast h(t) hi/lo in 4 pipelined cp.async groups (k-quarters)
            const __nv_bfloat16* hh = g_hh[t & 1];
            const __nv_bfloat16* hl = g_hl[t & 1];
#pragma unroll
            for (int grp = 0; grp < 4; ++grp) {
#pragma unroll
                for (int i = 0; i < 8; ++i) {
                    int item = i * 128 + tid;          // 0..1023
                    int bb = item >> 4, uu = item & 15;
                    uint32_t u = (uint32_t)(grp * 16 + uu);
                    uint32_t d = (uint32_t)bb * 1024u + ((u ^ (uint32_t)(bb & 7)) << 4);
                    const size_t go = (size_t)bb * 512 + u * 8;
                    cpa16(sbAh + d, hh + go);
                    cpa16(sbAl + d, hl + go);
                }
                CPA_COMMIT();
            }
        }

        // pre-activation loads (coalesced per warp, issue early)
        float pf0 = g_pre[((size_t)(t * 4 + 0) * 512 + h_0) * 64 + b];
        float pi0 = g_pre[((size_t)(t * 4 + 1) * 512 + h_0) * 64 + b];
        float pg0 = g_pre[((size_t)(t * 4 + 2) * 512 + h_0) * 64 + b];
        float po0 = g_pre[((size_t)(t * 4 + 3) * 512 + h_0) * 64 + b];
        float pf1 = g_pre[((size_t)(t * 4 + 0) * 512 + h_1) * 64 + b];
        float pi1 = g_pre[((size_t)(t * 4 + 1) * 512 + h_1) * 64 + b];
        float pg1 = g_pre[((size_t)(t * 4 + 2) * 512 + h_1) * 64 + b];
        float po1 = g_pre[((size_t)(t * 4 + 3) * 512 + h_1) * 64 + b];

        float c0[4] = {0.f, 0.f, 0.f, 0.f};
        float c1[4] = {0.f, 0.f, 0.f, 0.f};

        if (t > 0) {
#pragma unroll
            for (int q = 0; q < 4; ++q) {
                if      (q == 0) { CPA_WAIT3(); }
                else if (q == 1) { CPA_WAIT2(); }
                else if (q == 2) { CPA_WAIT1(); }
                else             { CPA_WAIT0(); }
                __syncthreads();
#pragma unroll
                for (int kk = 0; kk < 8; ++kk) {
                    const int kk16 = q * 8 + kk;
                    const uint32_t uA = (((uint32_t)(2 * kk16) + aSel) ^ aXor) << 4;
                    const uint32_t uB = (((uint32_t)(2 * kk16) + bSel) ^ bXor) << 4;
                    uint32_t aH[4], aL[4], bH[4], bL[4];
                    ldsm4(aH[0], aH[1], aH[2], aH[3], aBaseH + uA);
                    ldsm4(aL[0], aL[1], aL[2], aL[3], aBaseL + uA);
                    ldsm4(bH[0], bH[1], bH[2], bH[3], bBaseH + uB);
                    ldsm4(bL[0], bL[1], bL[2], bL[3], bBaseL + uB);
                    mma16816(c0, aH, bH);     mma16816(c1, aH, bH + 2);
                    mma16816(c0, aH, bL);     mma16816(c1, aH, bL + 2);
                    mma16816(c0, aL, bH);     mma16816(c1, aL, bH + 2);
                }
            }
        }

        // fragment exchange: lane pairs swap so each lane holds f,i,g,o
        float d0f, d0i, d0g, d0o, d1f, d1i, d1g, d1o;
        {
            float x0 = __shfl_xor_sync(0xffffffffu, c0[0], 1);
            float x1 = __shfl_xor_sync(0xffffffffu, c0[1], 1);
            float x2 = __shfl_xor_sync(0xffffffffu, c0[2], 1);
            float x3 = __shfl_xor_sync(0xffffffffu, c0[3], 1);
            if (!odd) { d0f = c0[0]; d0i = c0[1]; d0g = x0;   d0o = x1;   }
            else      { d0f = x2;    d0i = x3;    d0g = c0[2]; d0o = c0[3]; }
            float y0 = __shfl_xor_sync(0xffffffffu, c1[0], 1);
            float y1 = __shfl_xor_sync(0xffffffffu, c1[1], 1);
            float y2 = __shfl_xor_sync(0xffffffffu, c1[2], 1);
            float y3 = __shfl_xor_sync(0xffffffffu, c1[3], 1);
            if (!odd) { d1f = c1[0]; d1i = c1[1]; d1g = y0;   d1o = y1;   }
            else      { d1f = y2;    d1i = y3;    d1g = c1[2]; d1o = c1[3]; }
        }

        float f0 = sig_(pf0 + d0f + bf0);
        float i0 = sig_(pi0 + d0i + bi0);
        float gg0 = tanh_(pg0 + d0g + bg0);
        float o0 = sig_(po0 + d0o + bo0);
        cst0 = f0 * cst0 + i0 * gg0;
        float hv0 = o0 * tanh_(cst0);

        float f1 = sig_(pf1 + d1f + bf1);
        float i1 = sig_(pi1 + d1i + bi1);
        float gg1 = tanh_(pg1 + d1g + bg1);
        float o1 = sig_(po1 + d1o + bo1);
        cst1 = f1 * cst1 + i1 * gg1;
        float hv1 = o1 * tanh_(cst1);

        if (t == 255) {
            out[320 + b * 512 + h_0]         = hv0;
            out[320 + 32768 + b * 512 + h_0] = cst0;
            out[320 + b * 512 + h_1]         = hv1;
            out[320 + 32768 + b * 512 + h_1] = cst1;
        } else {
            __nv_bfloat16 h0h = __float2bfloat16(hv0);
            __nv_bfloat16 h0l = __float2bfloat16(hv0 - __bfloat162float(h0h));
            __nv_bfloat16 h1h = __float2bfloat16(hv1);
            __nv_bfloat16 h1l = __float2bfloat16(hv1 - __bfloat162float(h1h));
            const int nb = (t + 1) & 1;
            g_hh[nb][b * 512 + h_0] = h0h;  g_hl[nb][b * 512 + h_0] = h0l;
            g_hh[nb][b * 512 + h_1] = h1h;  g_hl[nb][b * 512 + h_1] = h1l;
            // release arrival: bar orders all threads' stores before tid0's red
            __syncthreads();
            if (tid == 0) bar_arrive_release(&g_bar);
        }
    }
}

// ======================= Phase 3: output head ================================
__global__ void head_kernel(const float* __restrict__ Wl, const float* __restrict__ bl,
                            float* __restrict__ out)
{
    int b = blockIdx.x;
    int tid = threadIdx.x;
    int o = tid >> 5, lane = tid & 31;
    const float* hrow = out + 320 + b * 512;
    float s = 0.0f;
#pragma unroll 4
    for (int k = lane; k < 512; k += 32) s += hrow[k] * Wl[k * 5 + o];
#pragma unroll
    for (int m = 16; m; m >>= 1) s += __shfl_xor_sync(0xffffffffu, s, m);
    if (lane == 0) out[b * 5 + o] = s + bl[o];
}

// ======================= launch =============================================
extern "C" void kernel_launch(void* const* d_in, const int* in_sizes, int n_in,
                              void* d_out, int out_size)
{
    const int*   x   = (const int*)d_in[0];
    const float* emb = (const float*)d_in[1];
    const float* Wfx = (const float*)d_in[2];
    const float* Wfh = (const float*)d_in[3];
    const float* bf  = (const float*)d_in[4];
    const float* Wix = (const float*)d_in[5];
    const float* Wih = (const float*)d_in[6];
    const float* bi  = (const float*)d_in[7];
    const float* Wgx = (const float*)d_in[8];
    const float* Wgh = (const float*)d_in[9];
    const float* bg  = (const float*)d_in[10];
    const float* Wox = (const float*)d_in[11];
    const float* Woh = (const float*)d_in[12];
    const float* bo  = (const float*)d_in[13];
    const float* Wl  = (const float*)d_in[14];
    const float* bl  = (const float*)d_in[15];
    float* out = (float*)d_out;

    cudaFuncSetAttribute(gemm_kernel, cudaFuncAttributeMaxDynamicSharedMemorySize, 196608);
    cudaFuncSetAttribute(lstm_kernel, cudaFuncAttributeMaxDynamicSharedMemorySize, 163840);

    prep_kernel<<<1, 32>>>();
    prep_w_kernel<<<4 * 16 * 128, 256>>>(Wfx, Wix, Wgx, Wox);
    prep_a_kernel<<<16384, 128>>>(x, emb);
    gemm_kernel<<<dim3(16, 128), 256, 196608>>>();
    dummy_kernel<<<1, 32>>>();
    lstm_kernel<<<128, 128, 163840>>>(Wfh, Wih, Wgh, Woh, bf, bi, bg, bo, out);
    head_kernel<<<64, 160>>>(Wl, bl, out);
}